// round 1
// baseline (speedup 1.0000x reference)
#include <cuda_runtime.h>

#define N 256
#define D 128

// Scratch (no allocations allowed in kernel_launch)
__device__ int   g_labels[N];
__device__ float g_norm[N];
__device__ float g_d[N * N];
__device__ float g_psum[N];
__device__ int   g_pcnt[N];

// Kernel 1: normalize labels (int64 vs int32 autodetect) + per-row squared norms.
// raw is viewed as int32; reading first 1024 bytes is safe for either dtype.
__global__ void prep_kernel(const int* __restrict__ raw,
                            const float* __restrict__ emb) {
    __shared__ int flag;
    int t = threadIdx.x;  // 0..255
    if (t == 0) flag = 0;
    __syncthreads();
    // If labels are int64 little-endian, every odd int32 word is the zero high half.
    if (t < 128 && raw[2 * t + 1] != 0) atomicOr(&flag, 1);
    __syncthreads();
    int lab = (flag == 0) ? raw[2 * t] : raw[t];
    g_labels[t] = lab;

    // Squared norm of row t
    const float4* r = reinterpret_cast<const float4*>(emb + t * D);
    float s = 0.f;
#pragma unroll
    for (int q = 0; q < D / 4; q++) {
        float4 v = __ldg(r + q);
        s += v.x * v.x + v.y * v.y + v.z * v.z + v.w * v.w;
    }
    g_norm[t] = s;
}

// Kernel 2: pairwise distances. Block i computes d[i, :].
__global__ void dist_kernel(const float* __restrict__ emb) {
    __shared__ float s_ai[D];
    int i = blockIdx.x;
    int k = threadIdx.x;  // 0..255
    if (k < D) s_ai[k] = emb[i * D + k];
    __syncthreads();

    const float4* rk = reinterpret_cast<const float4*>(emb + k * D);
    const float4* ri = reinterpret_cast<const float4*>(s_ai);
    float dot = 0.f;
#pragma unroll
    for (int q = 0; q < D / 4; q++) {
        float4 a = ri[q];
        float4 b = __ldg(rk + q);
        dot += a.x * b.x + a.y * b.y + a.z * b.z + a.w * b.w;
    }
    float d2 = g_norm[i] + g_norm[k] - 2.f * dot;
    // clip(d2, 0) then clip(., EPS) == max(d2, EPS) since EPS > 0
    g_d[i * N + k] = sqrtf(fmaxf(d2, 1e-4f));
}

// Kernel 3: per-(i,k) semi-hard negative scan over j. Block = i, thread = k.
__global__ void loss_kernel() {
    __shared__ float s_d[N];
    __shared__ int   s_lab[N];
    __shared__ float s_red[N];
    __shared__ int   s_cnt[N];

    int i = blockIdx.x;
    int k = threadIdx.x;
    s_d[k]   = g_d[i * N + k];
    s_lab[k] = g_labels[k];
    __syncthreads();

    int   lab_i  = s_lab[i];
    float d_ik   = s_d[k];
    bool  pos_ik = (s_lab[k] == lab_i) && (k != i);

    // M[i,j,k] requires pos[i,k]; semantics over j: (label[j] != label[i]) || (j == i)
    float minv   = 3.402823466e+38f;   // neg_inside candidate: min dd over M
    float maxneg = -3.402823466e+38f;  // neg_outside candidate: max dd over M & dd<0
    bool  found  = false;

    for (int j = 0; j < N; j++) {
        bool negj = (s_lab[j] != lab_i) || (j == i);  // warp-uniform predicate
        if (negj) {
            float dd = d_ik - s_d[j];
            minv = fminf(minv, dd);
            if (dd < 0.f) { maxneg = fmaxf(maxneg, dd); found = true; }
        }
    }

    float semi = found ? maxneg : minv;
    float val  = pos_ik ? fmaxf(0.f, semi + 1.0f) : 0.f;

    s_red[k] = val;
    s_cnt[k] = pos_ik ? 1 : 0;
    __syncthreads();
    // Deterministic fixed-order tree reduction
    for (int s = N / 2; s > 0; s >>= 1) {
        if (k < s) { s_red[k] += s_red[k + s]; s_cnt[k] += s_cnt[k + s]; }
        __syncthreads();
    }
    if (k == 0) { g_psum[i] = s_red[0]; g_pcnt[i] = s_cnt[0]; }
}

// Kernel 4: deterministic final reduction -> scalar loss.
__global__ void final_kernel(float* __restrict__ out) {
    __shared__ float s[N];
    __shared__ int   si[N];
    int k = threadIdx.x;
    s[k]  = g_psum[k];
    si[k] = g_pcnt[k];
    __syncthreads();
    for (int st = N / 2; st > 0; st >>= 1) {
        if (k < st) { s[k] += s[k + st]; si[k] += si[k + st]; }
        __syncthreads();
    }
    if (k == 0) out[0] = s[0] / (float)si[0];
}

extern "C" void kernel_launch(void* const* d_in, const int* in_sizes, int n_in,
                              void* d_out, int out_size) {
    const float* emb = (const float*)d_in[0];
    const int*   lab = (const int*)d_in[1];  // viewed as int32; prep_kernel autodetects int64
    (void)in_sizes; (void)n_in; (void)out_size;

    prep_kernel<<<1, 256>>>(lab, emb);
    dist_kernel<<<N, 256>>>(emb);
    loss_kernel<<<N, 256>>>();
    final_kernel<<<1, 256>>>((float*)d_out);
}

// round 2
// speedup vs baseline: 1.1306x; 1.1306x over previous
#include <cuda_runtime.h>

#define N 256
#define D 128

// Scratch (allocations forbidden)
__device__ float    g_psum[N];
__device__ int      g_pcnt[N];
__device__ unsigned g_count = 0;

__global__ void __launch_bounds__(256, 4)
fused_kernel(const int* __restrict__ raw,
             const float* __restrict__ emb,
             float* __restrict__ out) {
    __shared__ float s_ai[D];
    __shared__ float s_dn[N];      // masked distances: negj ? d_ij : -1
    __shared__ int   s_lab[N];
    __shared__ float s_red[N];
    __shared__ int   s_cnt[N];
    __shared__ float s_ni;
    __shared__ unsigned s_rank;

    const int i = blockIdx.x;
    const int k = threadIdx.x;

    // --- Label decode (int64 vs int32 autodetect via block-wide vote) ---
    // If labels are little-endian int64, every odd int32 word is zero.
    int odd_nonzero = (k < 128) ? (raw[2 * k + 1] != 0) : 0;
    int is_int32 = __syncthreads_or(odd_nonzero);
    s_lab[k] = is_int32 ? raw[k] : raw[2 * k];

    // --- Load anchor row i into shared ---
    if (k < D) s_ai[k] = emb[i * D + k];
    __syncthreads();

    // --- Thread k: dot(emb[i], emb[k]) and ||emb[k]||^2 in one pass ---
    const float4* rk = reinterpret_cast<const float4*>(emb + k * D);
    const float4* ri = reinterpret_cast<const float4*>(s_ai);
    float dot = 0.f, nk = 0.f;
#pragma unroll
    for (int q = 0; q < D / 4; q++) {
        float4 b = __ldg(rk + q);
        float4 a = ri[q];
        dot += a.x * b.x + a.y * b.y + a.z * b.z + a.w * b.w;
        nk  += b.x * b.x + b.y * b.y + b.z * b.z + b.w * b.w;
    }
    if (k == i) s_ni = nk;   // norm of anchor row
    __syncthreads();

    // d[i,k]; clip(.,0) then clip(.,EPS) == max(.,EPS)
    const float d_ik  = sqrtf(fmaxf(s_ni + nk - 2.f * dot, 1e-4f));
    const int   lab_i = s_lab[i];
    const bool  negk  = (s_lab[k] != lab_i) || (k == i);  // j-membership of index k
    const bool  pos_ik = (s_lab[k] == lab_i) && (k != i);

    // Masked distance array for the j-scan (d >= 0.01 > -1, so -1 never passes "> d_ik")
    s_dn[k]  = negk ? d_ik : -1.0f;
    s_red[k] = negk ? d_ik : -1.0f;
    __syncthreads();

    // --- maxd = max_j { d_ij : negj }  (k-independent; set nonempty since j=i qualifies) ---
#pragma unroll
    for (int s = N / 2; s > 0; s >>= 1) {
        if (k < s) s_red[k] = fmaxf(s_red[k], s_red[k + s]);
        __syncthreads();
    }
    const float maxd = s_red[0];
    __syncthreads();  // protect s_red before reuse below

    // --- Per-k scan: m = min { d_ij : negj, d_ij > d_ik } ---
    const float4* dn4 = reinterpret_cast<const float4*>(s_dn);
    float m = 3.402823466e+38f;
#pragma unroll 8
    for (int q = 0; q < N / 4; q++) {
        float4 v = dn4[q];  // LDS.128 broadcast
        if (v.x > d_ik) m = fminf(m, v.x);
        if (v.y > d_ik) m = fminf(m, v.y);
        if (v.z > d_ik) m = fminf(m, v.z);
        if (v.w > d_ik) m = fminf(m, v.w);
    }
    // mask_final[i,k] <=> exists d_ij > d_ik in negj set <=> maxd > d_ik
    const float semi = (maxd > d_ik) ? (d_ik - m) : (d_ik - maxd);
    const float val  = pos_ik ? fmaxf(0.f, semi + 1.0f) : 0.f;

    // --- Block reduction (fixed order, deterministic) ---
    s_red[k] = val;
    s_cnt[k] = pos_ik ? 1 : 0;
    __syncthreads();
#pragma unroll
    for (int s = N / 2; s > 0; s >>= 1) {
        if (k < s) { s_red[k] += s_red[k + s]; s_cnt[k] += s_cnt[k + s]; }
        __syncthreads();
    }

    if (k == 0) {
        g_psum[i] = s_red[0];
        g_pcnt[i] = s_cnt[0];
        __threadfence();
        s_rank = atomicAdd(&g_count, 1u);
    }
    __syncthreads();

    // --- Last block: deterministic final reduction -> scalar ---
    if (s_rank == N - 1) {
        s_red[k] = g_psum[k];
        s_cnt[k] = g_pcnt[k];
        __syncthreads();
#pragma unroll
        for (int s = N / 2; s > 0; s >>= 1) {
            if (k < s) { s_red[k] += s_red[k + s]; s_cnt[k] += s_cnt[k + s]; }
            __syncthreads();
        }
        if (k == 0) {
            out[0] = s_red[0] / (float)s_cnt[0];
            g_count = 0;  // reset for next graph replay
        }
    }
}

extern "C" void kernel_launch(void* const* d_in, const int* in_sizes, int n_in,
                              void* d_out, int out_size) {
    const float* emb = (const float*)d_in[0];
    const int*   lab = (const int*)d_in[1];  // int32 view; kernel autodetects int64
    (void)in_sizes; (void)n_in; (void)out_size;

    fused_kernel<<<N, 256>>>(lab, emb, (float*)d_out);
}

// round 3
// speedup vs baseline: 2.2059x; 1.9512x over previous
#include <cuda_runtime.h>

#define N 256
#define D 128
#define D4 (D / 4)      // 32 float4 per row
#define PAD4 33         // padded row stride in float4 (132 floats -> conflict-free min phases)

// Scratch (allocations forbidden)
__device__ float    g_psum[128];
__device__ float    g_pcnt[128];
__device__ unsigned g_count = 0;

// Dynamic shared layout (float4 units):
//   s_e   [0 .. 256*33)          embedding rows, padded
//   s_red [256*33 .. +256)       float4-per-thread reduction array
// then (float units):
//   s_dn0[256], s_dn1[256], s_norm[256], s_lab[256](int)
#define SMEM_BYTES ((N * PAD4 + N) * 16 + 3 * N * 4 + N * 4)

extern __shared__ float4 s4[];

__global__ void __launch_bounds__(256, 1)
fused_kernel(const int* __restrict__ raw,
             const float* __restrict__ emb,
             float* __restrict__ out) {
    float4* s_e    = s4;
    float4* s_red  = s4 + N * PAD4;
    float*  s_dn0  = (float*)(s_red + N);
    float*  s_dn1  = s_dn0 + N;
    float*  s_norm = s_dn1 + N;
    int*    s_lab  = (int*)(s_norm + N);
    __shared__ unsigned s_rank;

    const int t  = threadIdx.x;
    const int b  = blockIdx.x;
    const int i0 = 2 * b, i1 = 2 * b + 1;

    // --- Label decode (int64 vs int32 autodetect via block vote) ---
    int odd_nonzero = (t < 128) ? (raw[2 * t + 1] != 0) : 0;
    int is_int32 = __syncthreads_or(odd_nonzero);
    s_lab[t] = is_int32 ? raw[t] : raw[2 * t];

    // --- Coalesced relay: global -> padded shared (whole matrix, 128KB) ---
    const float4* e4 = reinterpret_cast<const float4*>(emb);
#pragma unroll
    for (int j = 0; j < 32; j++) {
        int f = t + j * 256;                    // float4 index 0..8191, coalesced
        float4 v = __ldg(e4 + f);
        s_e[(f >> 5) * PAD4 + (f & 31)] = v;    // row f/32, col f%32
    }
    __syncthreads();

    // --- Per-thread: own-row norm + dots against both anchors ---
    const float4* row = s_e + t * PAD4;         // 4-phase LDS.128, conflict-free
    const float4* a0  = s_e + i0 * PAD4;        // broadcast
    const float4* a1  = s_e + i1 * PAD4;        // broadcast
    float dot0 = 0.f, dot1 = 0.f, nk = 0.f;
#pragma unroll
    for (int q = 0; q < D4; q++) {
        float4 r = row[q], x = a0[q], y = a1[q];
        dot0 += r.x * x.x + r.y * x.y + r.z * x.z + r.w * x.w;
        dot1 += r.x * y.x + r.y * y.y + r.z * y.z + r.w * y.w;
        nk   += r.x * r.x + r.y * r.y + r.z * r.z + r.w * r.w;
    }
    s_norm[t] = nk;
    __syncthreads();

    const float n0 = s_norm[i0], n1 = s_norm[i1];
    // clip(.,0) then clip(.,EPS) == max(.,EPS)
    const float d0 = sqrtf(fmaxf(n0 + nk - 2.f * dot0, 1e-4f));
    const float d1 = sqrtf(fmaxf(n1 + nk - 2.f * dot1, 1e-4f));

    const int lk = s_lab[t], l0 = s_lab[i0], l1 = s_lab[i1];
    const bool neg0 = (lk != l0) || (t == i0);
    const bool neg1 = (lk != l1) || (t == i1);
    const bool pos0 = (lk == l0) && (t != i0);
    const bool pos1 = (lk == l1) && (t != i1);

    // Masked distance arrays (d >= 0.01 > -1, so -1 never passes "> d")
    const float dn0 = neg0 ? d0 : -1.f;
    const float dn1 = neg1 ? d1 : -1.f;
    s_dn0[t] = dn0;
    s_dn1[t] = dn1;
    s_red[t] = make_float4(dn0, dn1, 0.f, 0.f);
    __syncthreads();

    // --- maxd per anchor (k-independent; j=i always in set) ---
#pragma unroll
    for (int s = N / 2; s > 0; s >>= 1) {
        if (t < s) {
            float4 a = s_red[t], c = s_red[t + s];
            a.x = fmaxf(a.x, c.x);
            a.y = fmaxf(a.y, c.y);
            s_red[t] = a;
        }
        __syncthreads();
    }
    const float max0 = s_red[0].x, max1 = s_red[0].y;
    __syncthreads();   // protect s_red before reuse

    // --- Per-k masked successor-min scan (both anchors interleaved) ---
    const float4* p0 = reinterpret_cast<const float4*>(s_dn0);
    const float4* p1 = reinterpret_cast<const float4*>(s_dn1);
    float m0 = 3.402823466e+38f, m1 = 3.402823466e+38f;
#pragma unroll 8
    for (int q = 0; q < N / 4; q++) {
        float4 u = p0[q];   // broadcast LDS.128
        float4 v = p1[q];
        if (u.x > d0) m0 = fminf(m0, u.x);
        if (u.y > d0) m0 = fminf(m0, u.y);
        if (u.z > d0) m0 = fminf(m0, u.z);
        if (u.w > d0) m0 = fminf(m0, u.w);
        if (v.x > d1) m1 = fminf(m1, v.x);
        if (v.y > d1) m1 = fminf(m1, v.y);
        if (v.z > d1) m1 = fminf(m1, v.z);
        if (v.w > d1) m1 = fminf(m1, v.w);
    }
    // mask_final <=> exists d_ij > d_ik <=> maxd > d_ik
    const float semi0 = (max0 > d0) ? (d0 - m0) : (d0 - max0);
    const float semi1 = (max1 > d1) ? (d1 - m1) : (d1 - max1);
    const float v0 = pos0 ? fmaxf(0.f, semi0 + 1.0f) : 0.f;
    const float v1 = pos1 ? fmaxf(0.f, semi1 + 1.0f) : 0.f;

    // --- Block reduction: (sum0, sum1, cnt0, cnt1) fixed order ---
    s_red[t] = make_float4(v0, v1, pos0 ? 1.f : 0.f, pos1 ? 1.f : 0.f);
    __syncthreads();
#pragma unroll
    for (int s = N / 2; s > 0; s >>= 1) {
        if (t < s) {
            float4 a = s_red[t], c = s_red[t + s];
            a.x += c.x; a.y += c.y; a.z += c.z; a.w += c.w;
            s_red[t] = a;
        }
        __syncthreads();
    }

    if (t == 0) {
        float4 r = s_red[0];
        g_psum[b] = r.x + r.y;
        g_pcnt[b] = r.z + r.w;
        __threadfence();
        s_rank = atomicAdd(&g_count, 1u);
    }
    __syncthreads();

    // --- Last block: deterministic final reduction -> scalar ---
    if (s_rank == 127) {
        float ps = (t < 128) ? g_psum[t] : 0.f;
        float pc = (t < 128) ? g_pcnt[t] : 0.f;
        s_red[t] = make_float4(ps, pc, 0.f, 0.f);
        __syncthreads();
#pragma unroll
        for (int s = N / 2; s > 0; s >>= 1) {
            if (t < s) {
                float4 a = s_red[t], c = s_red[t + s];
                a.x += c.x; a.y += c.y;
                s_red[t] = a;
            }
            __syncthreads();
        }
        if (t == 0) {
            out[0] = s_red[0].x / s_red[0].y;
            g_count = 0;   // reset for next graph replay
        }
    }
}

extern "C" void kernel_launch(void* const* d_in, const int* in_sizes, int n_in,
                              void* d_out, int out_size) {
    const float* emb = (const float*)d_in[0];
    const int*   lab = (const int*)d_in[1];  // int32 view; kernel autodetects int64
    (void)in_sizes; (void)n_in; (void)out_size;

    cudaFuncSetAttribute(fused_kernel,
                         cudaFuncAttributeMaxDynamicSharedMemorySize, SMEM_BYTES);
    fused_kernel<<<128, 256, SMEM_BYTES>>>(lab, emb, (float*)d_out);
}

// round 4
// speedup vs baseline: 3.0831x; 1.3976x over previous
#include <cuda_runtime.h>

#define N 256
#define D 128
#define PAD4 33          // padded row stride in float4 -> conflict-free 4-phase LDS.128
#define T 512            // threads per block
#define GRID 128         // 2 anchors per block

// Scratch (allocations forbidden)
__device__ float2   g_part[GRID];
__device__ unsigned g_count = 0;

// Dynamic shared (float4 units then tail):
//   s_e [N*PAD4]  embedding rows, padded
//   s_p [T]       float4 partials (dot0,dot1,nk,-) ; aliased later as s_m float2[T]
// floats tail: dn0[N], dn1[N], lab[N](int), wmax[8] f2, ws[8] f2, nv[2]
#define SMEM_BYTES ((N * PAD4 + T) * 16 + 2 * N * 4 + N * 4 + 8 * 8 + 8 * 8 + 2 * 4)

extern __shared__ float4 s4[];

__global__ void __launch_bounds__(T, 1)
fused_kernel(const int* __restrict__ raw,
             const float* __restrict__ emb,
             float* __restrict__ out) {
    float4* s_e   = s4;
    float4* s_p   = s4 + N * PAD4;
    float2* s_m   = (float2*)s_p;            // alias: reused after s_p is consumed
    float*  s_dn0 = (float*)(s_p + T);
    float*  s_dn1 = s_dn0 + N;
    int*    s_lab = (int*)(s_dn1 + N);
    float2* s_wmax = (float2*)(s_lab + N);
    float2* s_ws   = s_wmax + 8;
    float*  s_nv   = (float*)(s_ws + 8);
    __shared__ unsigned s_rank;

    const int t    = threadIdx.x;
    const int k    = t & (N - 1);
    const int h    = t >> 8;                  // half index 0/1
    const int lane = t & 31;
    const int w    = t >> 5;                  // warp id 0..15
    const int b    = blockIdx.x;
    const int i0   = 2 * b, i1 = 2 * b + 1;

    // --- Issue async relay: global -> padded shared (whole 128KB matrix) ---
    const float4* e4 = reinterpret_cast<const float4*>(emb);
#pragma unroll
    for (int j = 0; j < 16; j++) {
        int f = t + j * T;                                   // coalesced float4 idx
        unsigned dst = (unsigned)__cvta_generic_to_shared(
            s_e + (f >> 5) * PAD4 + (f & 31));
        asm volatile("cp.async.ca.shared.global [%0], [%1], 16;\n"
                     :: "r"(dst), "l"(e4 + f));
    }
    asm volatile("cp.async.commit_group;\n");

    // --- Label decode while copies fly (int64 vs int32 autodetect) ---
    int odd_nonzero = (t < 128) ? (raw[2 * t + 1] != 0) : 0;
    int is_int32 = __syncthreads_or(odd_nonzero);
    if (t < N) s_lab[t] = is_int32 ? raw[t] : raw[2 * t];

    asm volatile("cp.async.wait_group 0;\n");
    __syncthreads();                                          // bar A

    // --- Half-row dot partials: thread (k,h) covers dims [h*64, h*64+64) ---
    const float4* row = s_e + k * PAD4 + h * 16;
    const float4* a0  = s_e + i0 * PAD4 + h * 16;             // broadcast
    const float4* a1  = s_e + i1 * PAD4 + h * 16;             // broadcast
    float dot0 = 0.f, dot1 = 0.f, nk = 0.f;
#pragma unroll
    for (int q = 0; q < 16; q++) {
        float4 r = row[q], x = a0[q], y = a1[q];
        dot0 += r.x * x.x + r.y * x.y + r.z * x.z + r.w * x.w;
        dot1 += r.x * y.x + r.y * y.y + r.z * y.z + r.w * y.w;
        nk   += r.x * r.x + r.y * r.y + r.z * r.z + r.w * r.w;
    }
    s_p[t] = make_float4(dot0, dot1, nk, 0.f);
    __syncthreads();                                          // bar B

    // --- Combine halves (both h compute identically -> identical d values) ---
    {
        float4 pa = s_p[k], pb = s_p[k + N];
        dot0 = pa.x + pb.x;
        dot1 = pa.y + pb.y;
        nk   = pa.z + pb.z;
    }
    if (t == i0) s_nv[0] = nk;                                // h==0 thread
    if (t == i1) s_nv[1] = nk;
    __syncthreads();                                          // bar C

    // d[i,k]; clip(.,0) then clip(.,EPS) == max(.,EPS)
    const float d0 = sqrtf(fmaxf(s_nv[0] + nk - 2.f * dot0, 1e-4f));
    const float d1 = sqrtf(fmaxf(s_nv[1] + nk - 2.f * dot1, 1e-4f));

    const int lk = s_lab[k], l0 = s_lab[i0], l1 = s_lab[i1];
    const bool neg0 = (lk != l0) || (k == i0);
    const bool neg1 = (lk != l1) || (k == i1);
    const bool pos0 = (lk == l0) && (k != i0);
    const bool pos1 = (lk == l1) && (k != i1);

    // Masked distances (d >= 0.01 > -1, so -1 never passes "> d")
    const float dn0 = neg0 ? d0 : -1.f;
    const float dn1 = neg1 ? d1 : -1.f;
    if (h == 0) { s_dn0[k] = dn0; s_dn1[k] = dn1; }
    __syncthreads();                                          // bar D (s_dn ready)

    // --- Block max of dn0/dn1 via warp shuffles (fixed order, deterministic) ---
    {
        float a = dn0, c = dn1;
#pragma unroll
        for (int off = 16; off > 0; off >>= 1) {
            a = fmaxf(a, __shfl_xor_sync(0xffffffffu, a, off));
            c = fmaxf(c, __shfl_xor_sync(0xffffffffu, c, off));
        }
        if (lane == 0 && h == 0) s_wmax[w] = make_float2(a, c);
    }

    // --- Half-range masked successor-min scan: j in [h*128, h*128+128) ---
    const float4* p0 = reinterpret_cast<const float4*>(s_dn0) + h * 32;
    const float4* p1 = reinterpret_cast<const float4*>(s_dn1) + h * 32;
    float m0 = 3.402823466e+38f, m1 = 3.402823466e+38f;
#pragma unroll 8
    for (int q = 0; q < 32; q++) {
        float4 u = p0[q];                                     // broadcast LDS.128
        float4 v = p1[q];
        if (u.x > d0) m0 = fminf(m0, u.x);
        if (u.y > d0) m0 = fminf(m0, u.y);
        if (u.z > d0) m0 = fminf(m0, u.z);
        if (u.w > d0) m0 = fminf(m0, u.w);
        if (v.x > d1) m1 = fminf(m1, v.x);
        if (v.y > d1) m1 = fminf(m1, v.y);
        if (v.z > d1) m1 = fminf(m1, v.z);
        if (v.w > d1) m1 = fminf(m1, v.w);
    }
    s_m[t] = make_float2(m0, m1);
    __syncthreads();                                          // bar E (wmax + s_m)

    // --- Finalize per-k, then block sum (h==0 warps only) ---
    if (h == 0) {
        float max0 = -1.f, max1 = -1.f;
#pragma unroll
        for (int q = 0; q < 8; q++) {
            float2 wm = s_wmax[q];                            // broadcast
            max0 = fmaxf(max0, wm.x);
            max1 = fmaxf(max1, wm.y);
        }
        float2 ma = s_m[k], mb = s_m[k + N];
        m0 = fminf(ma.x, mb.x);
        m1 = fminf(ma.y, mb.y);
        // mask_final <=> exists d_ij > d_ik <=> maxd > d_ik
        const float semi0 = (max0 > d0) ? (d0 - m0) : (d0 - max0);
        const float semi1 = (max1 > d1) ? (d1 - m1) : (d1 - max1);
        float sv = (pos0 ? fmaxf(0.f, semi0 + 1.0f) : 0.f)
                 + (pos1 ? fmaxf(0.f, semi1 + 1.0f) : 0.f);
        float sc = (pos0 ? 1.f : 0.f) + (pos1 ? 1.f : 0.f);
#pragma unroll
        for (int off = 16; off > 0; off >>= 1) {
            sv += __shfl_xor_sync(0xffffffffu, sv, off);
            sc += __shfl_xor_sync(0xffffffffu, sc, off);
        }
        if (lane == 0) s_ws[w] = make_float2(sv, sc);
    }
    __syncthreads();                                          // bar F

    if (t < 32) {
        float2 r = (lane < 8) ? s_ws[lane] : make_float2(0.f, 0.f);
#pragma unroll
        for (int off = 4; off > 0; off >>= 1) {
            r.x += __shfl_xor_sync(0xffffffffu, r.x, off);
            r.y += __shfl_xor_sync(0xffffffffu, r.y, off);
        }
        if (lane == 0) {
            g_part[b] = r;
            __threadfence();
            s_rank = atomicAdd(&g_count, 1u);
        }
    }
    __syncthreads();                                          // bar G

    // --- Last block: deterministic final reduction over 128 partials ---
    if (s_rank == GRID - 1 && t < 32) {
        float sx = 0.f, sy = 0.f;
#pragma unroll
        for (int q = 0; q < 4; q++) {
            const float2* gp = (const float2*)g_part + lane + q * 32;
            float2 v;
            asm volatile("ld.global.cg.v2.f32 {%0,%1}, [%2];"
                         : "=f"(v.x), "=f"(v.y) : "l"(gp));
            sx += v.x; sy += v.y;
        }
#pragma unroll
        for (int off = 16; off > 0; off >>= 1) {
            sx += __shfl_xor_sync(0xffffffffu, sx, off);
            sy += __shfl_xor_sync(0xffffffffu, sy, off);
        }
        if (lane == 0) {
            out[0] = sx / sy;
            g_count = 0;                                      // reset for replay
        }
    }
}

extern "C" void kernel_launch(void* const* d_in, const int* in_sizes, int n_in,
                              void* d_out, int out_size) {
    const float* emb = (const float*)d_in[0];
    const int*   lab = (const int*)d_in[1];  // int32 view; kernel autodetects int64
    (void)in_sizes; (void)n_in; (void)out_size;

    cudaFuncSetAttribute(fused_kernel,
                         cudaFuncAttributeMaxDynamicSharedMemorySize, SMEM_BYTES);
    fused_kernel<<<GRID, T, SMEM_BYTES>>>(lab, emb, (float*)d_out);
}

// round 5
// speedup vs baseline: 3.1015x; 1.0060x over previous
#include <cuda_runtime.h>

#define N 256
#define PAD4 33          // padded row stride in float4 -> conflict-free 4-phase LDS.128
#define T 512
#define GRID 128         // 2 anchors per block
#define MAXE 512         // worst case: all labels identical -> 2*255 entries

// Scratch (allocations forbidden)
__device__ float2   g_part[GRID];
__device__ unsigned g_count = 0;

// Dynamic shared layout:
//   s_e   [N*PAD4] float4   embeddings, padded
//   s_p   [T]      float4   dot partials
//   s_dn0[N], s_dn1[N] f32  masked distance arrays
//   s_lab[N] int
//   s_wmax[8] float2, s_c0[8] int, s_c1[8] int
//   s_ed[MAXE] f32 (sign = anchor), s_val[MAXE] f32, s_nv[2] f32
#define SMEM_BYTES ((N * PAD4 + T) * 16 + 2 * N * 4 + N * 4 + 8 * 8 + 16 * 4 \
                    + MAXE * 4 + MAXE * 4 + 2 * 4)

extern __shared__ float4 s4[];

__global__ void __launch_bounds__(T, 1)
fused_kernel(const int* __restrict__ raw,
             const float* __restrict__ emb,
             float* __restrict__ out) {
    float4* s_e    = s4;
    float4* s_p    = s4 + N * PAD4;
    float*  s_dn0  = (float*)(s_p + T);
    float*  s_dn1  = s_dn0 + N;
    int*    s_lab  = (int*)(s_dn1 + N);
    float2* s_wmax = (float2*)(s_lab + N);
    int*    s_c0   = (int*)(s_wmax + 8);
    int*    s_c1   = s_c0 + 8;
    float*  s_ed   = (float*)(s_c1 + 8);
    float*  s_val  = s_ed + MAXE;
    float*  s_nv   = s_val + MAXE;

    const int t    = threadIdx.x;
    const int k    = t & (N - 1);
    const int h    = t >> 8;               // warps 0-7: h=0, warps 8-15: h=1
    const int lane = t & 31;
    const int w    = t >> 5;
    const int b    = blockIdx.x;
    const int i0   = 2 * b, i1 = 2 * b + 1;

    // --- Async relay: global -> padded shared (whole 128KB matrix) ---
    const float4* e4 = reinterpret_cast<const float4*>(emb);
#pragma unroll
    for (int j = 0; j < 16; j++) {
        int f = t + j * T;
        unsigned dst = (unsigned)__cvta_generic_to_shared(
            s_e + (f >> 5) * PAD4 + (f & 31));
        asm volatile("cp.async.ca.shared.global [%0], [%1], 16;\n"
                     :: "r"(dst), "l"(e4 + f));
    }
    asm volatile("cp.async.commit_group;\n");

    // --- Label decode while copies fly (int64 vs int32 autodetect) ---
    int odd_nonzero = (t < 128) ? (raw[2 * t + 1] != 0) : 0;
    int is_int32 = __syncthreads_or(odd_nonzero);
    if (t < N) s_lab[t] = is_int32 ? raw[t] : raw[2 * t];

    asm volatile("cp.async.wait_group 0;\n");
    __syncthreads();                                          // bar A

    // --- Half-row dot partials: thread (k,h) covers dims [h*64, h*64+64) ---
    const float4* row = s_e + k * PAD4 + h * 16;
    const float4* a0  = s_e + i0 * PAD4 + h * 16;             // broadcast
    const float4* a1  = s_e + i1 * PAD4 + h * 16;             // broadcast
    float dot0 = 0.f, dot1 = 0.f, nk = 0.f;
#pragma unroll
    for (int q = 0; q < 16; q++) {
        float4 r = row[q], x = a0[q], y = a1[q];
        dot0 += r.x * x.x + r.y * x.y + r.z * x.z + r.w * x.w;
        dot1 += r.x * y.x + r.y * y.y + r.z * y.z + r.w * y.w;
        nk   += r.x * r.x + r.y * r.y + r.z * r.z + r.w * r.w;
    }
    s_p[t] = make_float4(dot0, dot1, nk, 0.f);
    __syncthreads();                                          // bar B

    // --- Combine halves (both h end up with identical full values) ---
    {
        float4 pa = s_p[k], pb = s_p[k + N];
        dot0 = pa.x + pb.x;
        dot1 = pa.y + pb.y;
        nk   = pa.z + pb.z;
    }
    if (t == i0) s_nv[0] = nk;
    if (t == i1) s_nv[1] = nk;
    __syncthreads();                                          // bar C

    // d[i,k]; clip(.,0) then clip(.,EPS) == max(.,EPS)
    const float d0 = sqrtf(fmaxf(s_nv[0] + nk - 2.f * dot0, 1e-4f));
    const float d1 = sqrtf(fmaxf(s_nv[1] + nk - 2.f * dot1, 1e-4f));

    const int lk = s_lab[k], l0 = s_lab[i0], l1 = s_lab[i1];
    const bool neg0 = (lk != l0) || (k == i0);
    const bool neg1 = (lk != l1) || (k == i1);
    const bool pos0 = (lk == l0) && (k != i0);
    const bool pos1 = (lk == l1) && (k != i1);

    // Masked distances (d >= 0.01 > -1, -1 never passes "> d")
    const float dn0 = neg0 ? d0 : -1.f;
    const float dn1 = neg1 ? d1 : -1.f;

    unsigned b0 = 0, b1 = 0;
    if (w < 8) {                                              // h==0 warps own k space
        s_dn0[k] = dn0;
        s_dn1[k] = dn1;
        float a = dn0, c = dn1;
#pragma unroll
        for (int off = 16; off > 0; off >>= 1) {
            a = fmaxf(a, __shfl_xor_sync(0xffffffffu, a, off));
            c = fmaxf(c, __shfl_xor_sync(0xffffffffu, c, off));
        }
        b0 = __ballot_sync(0xffffffffu, pos0);
        b1 = __ballot_sync(0xffffffffu, pos1);
        if (lane == 0) {
            s_wmax[w] = make_float2(a, c);
            s_c0[w] = __popc(b0);
            s_c1[w] = __popc(b1);
        }
    }
    __syncthreads();                                          // bar D

    // --- Deterministic compaction slots + block maxd + total count ---
    int C0 = 0, C1 = 0, p0 = 0, p1 = 0;
    float max0 = -1.f, max1 = -1.f;
#pragma unroll
    for (int q = 0; q < 8; q++) {
        int c0 = s_c0[q], c1 = s_c1[q];
        if (q < w) { p0 += c0; p1 += c1; }
        C0 += c0; C1 += c1;
        float2 wm = s_wmax[q];
        max0 = fmaxf(max0, wm.x);
        max1 = fmaxf(max1, wm.y);
    }
    const int C = C0 + C1;

    if (w < 8) {
        unsigned lt = (1u << lane) - 1u;
        // Anchor0 entries in [0, C0): store +d0.  Anchor1 in [C0, C): store -d1.
        if (pos0) s_ed[p0 + __popc(b0 & lt)] = d0;
        if (pos1) s_ed[C0 + p1 + __popc(b1 & lt)] = -d1;
    }
    __syncthreads();                                          // bar E

    // --- Warp-cooperative successor-min scan, one entry per warp round ---
    for (int e = w; e < C; e += 16) {
        float dve = s_ed[e];                                  // broadcast
        const bool  a1f = (dve < 0.f);
        const float dv  = fabsf(dve);
        const float4* p = a1f ? (const float4*)s_dn1 : (const float4*)s_dn0;
        float4 u = p[lane], v = p[lane + 32];                 // conflict-free LDS.128
        float m = 3.402823466e+38f;
        if (u.x > dv) m = fminf(m, u.x);
        if (u.y > dv) m = fminf(m, u.y);
        if (u.z > dv) m = fminf(m, u.z);
        if (u.w > dv) m = fminf(m, u.w);
        if (v.x > dv) m = fminf(m, v.x);
        if (v.y > dv) m = fminf(m, v.y);
        if (v.z > dv) m = fminf(m, v.z);
        if (v.w > dv) m = fminf(m, v.w);
#pragma unroll
        for (int off = 16; off > 0; off >>= 1)
            m = fminf(m, __shfl_xor_sync(0xffffffffu, m, off));
        if (lane == 0) {
            const float mx = a1f ? max1 : max0;
            // mask_final <=> exists d_ij > d_ik <=> maxd > d_ik
            const float semi = (mx > dv) ? (dv - m) : (dv - mx);
            s_val[e] = fmaxf(0.f, semi + 1.0f);
        }
    }
    __syncthreads();                                          // bar F

    // --- Warp 0: fixed-order block sum + cross-block handoff ---
    if (t < 32) {
        float sv = 0.f;
        for (int e = lane; e < C; e += 32) sv += s_val[e];
#pragma unroll
        for (int off = 16; off > 0; off >>= 1)
            sv += __shfl_xor_sync(0xffffffffu, sv, off);

        unsigned rank = 0;
        if (lane == 0) {
            g_part[b] = make_float2(sv, (float)C);
            __threadfence();
            rank = atomicAdd(&g_count, 1u);
        }
        rank = __shfl_sync(0xffffffffu, rank, 0);

        // --- Last block: deterministic final reduction over 128 partials ---
        if (rank == GRID - 1) {
            float sx = 0.f, sy = 0.f;
#pragma unroll
            for (int q = 0; q < 4; q++) {
                const float2* gp = (const float2*)g_part + lane + q * 32;
                float2 vv;
                asm volatile("ld.global.cg.v2.f32 {%0,%1}, [%2];"
                             : "=f"(vv.x), "=f"(vv.y) : "l"(gp));
                sx += vv.x; sy += vv.y;
            }
#pragma unroll
            for (int off = 16; off > 0; off >>= 1) {
                sx += __shfl_xor_sync(0xffffffffu, sx, off);
                sy += __shfl_xor_sync(0xffffffffu, sy, off);
            }
            if (lane == 0) {
                out[0] = sx / sy;
                g_count = 0;                                  // reset for replay
            }
        }
    }
}

extern "C" void kernel_launch(void* const* d_in, const int* in_sizes, int n_in,
                              void* d_out, int out_size) {
    const float* emb = (const float*)d_in[0];
    const int*   lab = (const int*)d_in[1];  // int32 view; kernel autodetects int64
    (void)in_sizes; (void)n_in; (void)out_size;

    cudaFuncSetAttribute(fused_kernel,
                         cudaFuncAttributeMaxDynamicSharedMemorySize, SMEM_BYTES);
    fused_kernel<<<GRID, T, SMEM_BYTES>>>(lab, emb, (float*)d_out);
}